// round 4
// baseline (speedup 1.0000x reference)
#include <cuda_runtime.h>
#include <math_constants.h>

#define D_MODEL 1024
#define N_HEADS 16
#define D_HEAD  64
#define WINDOW  256
#define SEQ     2048
#define BATCH   2
#define M_ROWS  (BATCH * SEQ)   // 4096
#define QKV_LD  (3 * D_MODEL)   // 3072

// Scratch (allocation-free rule: __device__ globals)
__device__ float g_qkv[(size_t)M_ROWS * QKV_LD];   // [4096][3072]
__device__ float g_att[(size_t)M_ROWS * D_MODEL];  // [4096][1024]

// ---------------------------------------------------------------------------
// tf32 helpers
// ---------------------------------------------------------------------------
__device__ __forceinline__ float to_tf32(float x) {
    unsigned int u;
    asm("cvt.rna.tf32.f32 %0, %1;" : "=r"(u) : "f"(x));
    return __uint_as_float(u);
}

__device__ __forceinline__ void mma_tf32(float* c,
                                         unsigned a0, unsigned a1, unsigned a2, unsigned a3,
                                         unsigned b0, unsigned b1) {
    asm volatile(
        "mma.sync.aligned.m16n8k8.row.col.f32.tf32.tf32.f32 "
        "{%0,%1,%2,%3}, {%4,%5,%6,%7}, {%8,%9}, {%0,%1,%2,%3};\n"
        : "+f"(c[0]), "+f"(c[1]), "+f"(c[2]), "+f"(c[3])
        : "r"(a0), "r"(a1), "r"(a2), "r"(a3), "r"(b0), "r"(b1));
}

// ---------------------------------------------------------------------------
// Generic GEMM: C[M,N] = A[M,K] @ B[K,N] + bias[N]     (tf32 MMA, fp32 accum)
// Block tile 128x128, BK=32, 256 threads = 8 warps (4m x 2n), warp 32x64.
// Requires M%128==0, N%128==0, K%32==0 (true for all shapes here).
// ---------------------------------------------------------------------------
__global__ __launch_bounds__(256)
void gemm_tf32(const float* __restrict__ A, const float* __restrict__ B,
               const float* __restrict__ bias, float* __restrict__ C,
               int M, int N, int K) {
    __shared__ float As[128][36];   // [m][k], pad 36 -> conflict-free frag loads
    __shared__ float Bs[32][136];   // [k][n], pad 136

    const int tid  = threadIdx.x;
    const int lane = tid & 31;
    const int warp = tid >> 5;
    const int g    = lane >> 2;     // group id 0..7
    const int tg   = lane & 3;      // thread-in-group 0..3
    const int wm   = (warp & 3) * 32;
    const int wn   = (warp >> 2) * 64;
    const int bm   = blockIdx.y * 128;
    const int bn   = blockIdx.x * 128;

    float acc[2][8][4];
    #pragma unroll
    for (int i = 0; i < 2; i++)
        #pragma unroll
        for (int j = 0; j < 8; j++)
            #pragma unroll
            for (int k = 0; k < 4; k++) acc[i][j][k] = 0.f;

    const int ar = tid >> 3;          // 0..31
    const int ac = (tid & 7) << 2;    // 0..28
    const int br = tid >> 5;          // 0..7
    const int bc = (tid & 31) << 2;   // 0..124

    for (int kb = 0; kb < K; kb += 32) {
        #pragma unroll
        for (int p = 0; p < 4; p++) {
            int r = ar + p * 32;
            float4 v = *(const float4*)(A + (size_t)(bm + r) * K + kb + ac);
            As[r][ac + 0] = to_tf32(v.x);
            As[r][ac + 1] = to_tf32(v.y);
            As[r][ac + 2] = to_tf32(v.z);
            As[r][ac + 3] = to_tf32(v.w);
        }
        #pragma unroll
        for (int p = 0; p < 4; p++) {
            int r = br + p * 8;
            float4 v = *(const float4*)(B + (size_t)(kb + r) * N + bn + bc);
            Bs[r][bc + 0] = to_tf32(v.x);
            Bs[r][bc + 1] = to_tf32(v.y);
            Bs[r][bc + 2] = to_tf32(v.z);
            Bs[r][bc + 3] = to_tf32(v.w);
        }
        __syncthreads();

        #pragma unroll
        for (int ks = 0; ks < 4; ks++) {
            const int k8 = ks * 8;
            unsigned a[2][4];
            #pragma unroll
            for (int mt = 0; mt < 2; mt++) {
                int r = wm + mt * 16 + g;
                a[mt][0] = __float_as_uint(As[r][k8 + tg]);
                a[mt][1] = __float_as_uint(As[r + 8][k8 + tg]);
                a[mt][2] = __float_as_uint(As[r][k8 + tg + 4]);
                a[mt][3] = __float_as_uint(As[r + 8][k8 + tg + 4]);
            }
            unsigned b0[8], b1[8];
            #pragma unroll
            for (int nt = 0; nt < 8; nt++) {
                int cc = wn + nt * 8 + g;
                b0[nt] = __float_as_uint(Bs[k8 + tg][cc]);
                b1[nt] = __float_as_uint(Bs[k8 + tg + 4][cc]);
            }
            #pragma unroll
            for (int mt = 0; mt < 2; mt++)
                #pragma unroll
                for (int nt = 0; nt < 8; nt++)
                    mma_tf32(acc[mt][nt], a[mt][0], a[mt][1], a[mt][2], a[mt][3],
                             b0[nt], b1[nt]);
        }
        __syncthreads();
    }

    // epilogue: c0:(g,2tg) c1:(g,2tg+1) c2:(g+8,2tg) c3:(g+8,2tg+1)
    #pragma unroll
    for (int mt = 0; mt < 2; mt++) {
        #pragma unroll
        for (int nt = 0; nt < 8; nt++) {
            int r0 = bm + wm + mt * 16 + g;
            int c0 = bn + wn + nt * 8 + 2 * tg;
            float bv0 = bias[c0], bv1 = bias[c0 + 1];
            C[(size_t)r0 * N + c0]           = acc[mt][nt][0] + bv0;
            C[(size_t)r0 * N + c0 + 1]       = acc[mt][nt][1] + bv1;
            C[(size_t)(r0 + 8) * N + c0]     = acc[mt][nt][2] + bv0;
            C[(size_t)(r0 + 8) * N + c0 + 1] = acc[mt][nt][3] + bv1;
        }
    }
}

// ---------------------------------------------------------------------------
// Windowed attention (anti-causal: query i attends keys j in [i, i+255]).
// One block = (b, h, 64 queries). 5 key chunks of 64, online softmax.
// 256 threads as 16x16 grid, 4x4 micro-tiles, fp32 FFMA.
// ---------------------------------------------------------------------------
#define SMPAD 68
#define ATTN_SMEM ((4 * 64 * SMPAD + 3 * 64) * 4)

__global__ __launch_bounds__(256)
void attn_win(const float* __restrict__ qkv, float* __restrict__ out) {
    extern __shared__ float sm[];
    float* Qt   = sm;                  // [d][i]  64x68
    float* Kt   = Qt + 64 * SMPAD;     // [d][j]
    float* Vs   = Kt + 64 * SMPAD;     // [j][d]
    float* Pt   = Vs + 64 * SMPAD;     // [j][i]  scores -> probs, transposed
    float* mrow = Pt + 64 * SMPAD;     // [64]
    float* lrow = mrow + 64;
    float* frow = lrow + 64;

    const int tid = threadIdx.x;
    const int tx  = tid & 15;          // key / dh column group
    const int ty  = tid >> 4;          // query row group
    const int b   = blockIdx.z, h = blockIdx.y;
    const int qs  = blockIdx.x * 64;

    const int rr = tid >> 4;           // 0..15 (load row)
    const int d4 = (tid & 15) << 2;    // 0..60 (load col)

    // Q tile, transposed into shared
    const float* Qb = qkv + (size_t)(b * SEQ + qs) * QKV_LD + h * D_HEAD;
    #pragma unroll
    for (int p = 0; p < 4; p++) {
        int i = rr + p * 16;
        float4 v = *(const float4*)(Qb + (size_t)i * QKV_LD + d4);
        Qt[(d4 + 0) * SMPAD + i] = v.x;
        Qt[(d4 + 1) * SMPAD + i] = v.y;
        Qt[(d4 + 2) * SMPAD + i] = v.z;
        Qt[(d4 + 3) * SMPAD + i] = v.w;
    }
    if (tid < 64) { mrow[tid] = -CUDART_INF_F; lrow[tid] = 0.f; }

    float o[4][4];
    #pragma unroll
    for (int r = 0; r < 4; r++)
        #pragma unroll
        for (int c = 0; c < 4; c++) o[r][c] = 0.f;

    const float* Kbase = qkv + (size_t)(b * SEQ) * QKV_LD + D_MODEL + h * D_HEAD;
    const float* Vbase = Kbase + D_MODEL;

    for (int ch = 0; ch < 5; ch++) {
        __syncthreads();               // protect Qt(first)/Kt/Vs/Pt reuse
        const int j0 = qs + ch * 64;

        #pragma unroll
        for (int p = 0; p < 4; p++) {
            int jj = rr + p * 16;
            int jr = min(j0 + jj, SEQ - 1);     // clamp: OOB keys masked below
            float4 kv = *(const float4*)(Kbase + (size_t)jr * QKV_LD + d4);
            Kt[(d4 + 0) * SMPAD + jj] = kv.x;
            Kt[(d4 + 1) * SMPAD + jj] = kv.y;
            Kt[(d4 + 2) * SMPAD + jj] = kv.z;
            Kt[(d4 + 3) * SMPAD + jj] = kv.w;
            float4 vv = *(const float4*)(Vbase + (size_t)jr * QKV_LD + d4);
            *(float4*)(Vs + jj * SMPAD + d4) = vv;
        }
        __syncthreads();

        // GEMM1: S = Q K^T  (4x4 per thread)
        float s[4][4];
        #pragma unroll
        for (int r = 0; r < 4; r++)
            #pragma unroll
            for (int c = 0; c < 4; c++) s[r][c] = 0.f;
        #pragma unroll
        for (int d = 0; d < 64; d++) {
            float4 q4 = *(const float4*)(Qt + d * SMPAD + 4 * ty);
            float4 k4 = *(const float4*)(Kt + d * SMPAD + 4 * tx);
            s[0][0] += q4.x * k4.x; s[0][1] += q4.x * k4.y; s[0][2] += q4.x * k4.z; s[0][3] += q4.x * k4.w;
            s[1][0] += q4.y * k4.x; s[1][1] += q4.y * k4.y; s[1][2] += q4.y * k4.z; s[1][3] += q4.y * k4.w;
            s[2][0] += q4.z * k4.x; s[2][1] += q4.z * k4.y; s[2][2] += q4.z * k4.z; s[2][3] += q4.z * k4.w;
            s[3][0] += q4.w * k4.x; s[3][1] += q4.w * k4.y; s[3][2] += q4.w * k4.z; s[3][3] += q4.w * k4.w;
        }
        // mask + scale, store transposed [j][i]
        #pragma unroll
        for (int r = 0; r < 4; r++) {
            #pragma unroll
            for (int c = 0; c < 4; c++) {
                int qi = 4 * ty + r, jl = 4 * tx + c;
                int dj = ch * 64 + jl - qi;        // j - i
                bool keep = (dj >= 0) && (dj < WINDOW) && (j0 + jl < SEQ);
                Pt[jl * SMPAD + qi] = keep ? s[r][c] * 0.125f : -CUDART_INF_F;
            }
        }
        __syncthreads();

        // online softmax (one thread per query row)
        if (tid < 64) {
            float m = mrow[tid];
            float mc = -CUDART_INF_F;
            #pragma unroll
            for (int jl = 0; jl < 64; jl++) mc = fmaxf(mc, Pt[jl * SMPAD + tid]);
            float mn = fmaxf(m, mc);               // finite after chunk 0 (diag)
            float f  = __expf(m - mn);
            float ssum = 0.f;
            #pragma unroll
            for (int jl = 0; jl < 64; jl++) {
                float p = __expf(Pt[jl * SMPAD + tid] - mn);
                ssum += p;
                Pt[jl * SMPAD + tid] = p;
            }
            lrow[tid] = lrow[tid] * f + ssum;
            mrow[tid] = mn;
            frow[tid] = f;
        }
        __syncthreads();

        // rescale accumulators + GEMM2: O += P V
        float fr0 = frow[4 * ty + 0], fr1 = frow[4 * ty + 1];
        float fr2 = frow[4 * ty + 2], fr3 = frow[4 * ty + 3];
        #pragma unroll
        for (int c = 0; c < 4; c++) {
            o[0][c] *= fr0; o[1][c] *= fr1; o[2][c] *= fr2; o[3][c] *= fr3;
        }
        #pragma unroll
        for (int jl = 0; jl < 64; jl++) {
            float4 p4 = *(const float4*)(Pt + jl * SMPAD + 4 * ty);
            float4 v4 = *(const float4*)(Vs + jl * SMPAD + 4 * tx);
            o[0][0] += p4.x * v4.x; o[0][1] += p4.x * v4.y; o[0][2] += p4.x * v4.z; o[0][3] += p4.x * v4.w;
            o[1][0] += p4.y * v4.x; o[1][1] += p4.y * v4.y; o[1][2] += p4.y * v4.z; o[1][3] += p4.y * v4.w;
            o[2][0] += p4.z * v4.x; o[2][1] += p4.z * v4.y; o[2][2] += p4.z * v4.z; o[2][3] += p4.z * v4.w;
            o[3][0] += p4.w * v4.x; o[3][1] += p4.w * v4.y; o[3][2] += p4.w * v4.z; o[3][3] += p4.w * v4.w;
        }
    }

    // finalize: divide by l, write [B,S,H*dh]
    #pragma unroll
    for (int r = 0; r < 4; r++) {
        int qi = 4 * ty + r;
        float inv = 1.f / lrow[qi];
        float4 res = make_float4(o[r][0] * inv, o[r][1] * inv, o[r][2] * inv, o[r][3] * inv);
        *(float4*)(out + (size_t)(b * SEQ + qs + qi) * D_MODEL + h * D_HEAD + 4 * tx) = res;
    }
}

// ---------------------------------------------------------------------------
extern "C" void kernel_launch(void* const* d_in, const int* in_sizes, int n_in,
                              void* d_out, int out_size) {
    const float* x    = (const float*)d_in[0];   // [2,2048,1024]
    const float* Wqkv = (const float*)d_in[1];   // [1024,3072]
    const float* bqkv = (const float*)d_in[2];   // [3072]
    const float* Wout = (const float*)d_in[3];   // [1024,1024]
    const float* bout = (const float*)d_in[4];   // [1024]
    float* out = (float*)d_out;                  // [2,2048,1024] f32

    float *qkv, *att;
    cudaGetSymbolAddress((void**)&qkv, g_qkv);
    cudaGetSymbolAddress((void**)&att, g_att);

    cudaFuncSetAttribute(attn_win, cudaFuncAttributeMaxDynamicSharedMemorySize,
                         ATTN_SMEM);

    // 1) QKV projection: [4096,1024] @ [1024,3072] + b
    gemm_tf32<<<dim3(QKV_LD / 128, M_ROWS / 128), 256>>>(
        x, Wqkv, bqkv, qkv, M_ROWS, QKV_LD, D_MODEL);

    // 2) windowed attention
    attn_win<<<dim3(SEQ / 64, N_HEADS, BATCH), 256, ATTN_SMEM>>>(qkv, att);

    // 3) output projection: [4096,1024] @ [1024,1024] + b -> d_out
    gemm_tf32<<<dim3(D_MODEL / 128, M_ROWS / 128), 256>>>(
        att, Wout, bout, out, M_ROWS, D_MODEL, D_MODEL);
}